// round 4
// baseline (speedup 1.0000x reference)
#include <cuda_runtime.h>
#include <cuda_bf16.h>

// Problem constants (from reference setup_inputs)
#define B  4
#define C  64
#define H  128
#define W  128
#define O  64
#define KH 3
#define KW 3
#define K  9          // KH*KW
#define CK (C*K)      // 576
#define HW (H*W)      // 16384

#define TILE_P 32     // pixels per block (consecutive wo in one row)
#define NTHREADS 256

// Scratch (allocation-free rule: __device__ globals)
__device__ float g_xt[B * HW * C];        // NHWC transposed input, 16.8MB
__device__ float g_wq[CK * O];            // repacked weight [CK/4][O][4], 147KB

// ---------------------------------------------------------------------------
// Kernel A: NCHW -> NHWC transpose (per batch: [C][HW] -> [HW][C])
// ---------------------------------------------------------------------------
__global__ void transpose_kernel(const float* __restrict__ x) {
    __shared__ float tile[32][33];
    int b  = blockIdx.z;
    int c0 = blockIdx.y * 32;
    int s0 = blockIdx.x * 32;
    int tx = threadIdx.x, ty = threadIdx.y;   // block (32, 8)
    #pragma unroll
    for (int i = 0; i < 32; i += 8)
        tile[ty + i][tx] = x[(b * C + c0 + ty + i) * HW + s0 + tx];
    __syncthreads();
    #pragma unroll
    for (int i = 0; i < 32; i += 8)
        g_xt[(b * HW + s0 + ty + i) * C + c0 + tx] = tile[tx][ty + i];
}

// ---------------------------------------------------------------------------
// Kernel B: weight repack  W[o][c][kh][kw] -> Wq[ckb][o][i]  (ck = ckb*4+i)
// ---------------------------------------------------------------------------
__global__ void wq_kernel(const float* __restrict__ w) {
    int idx = blockIdx.x * 256 + threadIdx.x;
    if (idx < CK * O) {
        int i   = idx & 3;
        int o   = (idx >> 2) & (O - 1);
        int ckb = idx >> 8;
        int ck  = ckb * 4 + i;
        int c   = ck / K;
        int kk  = ck % K;
        g_wq[idx] = w[(o * C + c) * K + kk];
    }
}

// ---------------------------------------------------------------------------
// Main kernel: one block = (b, ho, 32 consecutive wo)
// ---------------------------------------------------------------------------
__global__ __launch_bounds__(NTHREADS, 2)
void deform_main_kernel(const float* __restrict__ offset,
                        const float* __restrict__ mask,
                        const float* __restrict__ bias,
                        float* __restrict__ out) {
    extern __shared__ float smem[];
    float* val   = smem;                         // [TILE_P][CK] = 32*576 floats
    int*   s_y0  = (int*)  (smem + TILE_P * CK); // [288]
    int*   s_x0  = s_y0 + K * TILE_P;
    float* s_w00 = (float*)(s_x0 + K * TILE_P);
    float* s_w01 = s_w00 + K * TILE_P;
    float* s_w10 = s_w01 + K * TILE_P;
    float* s_w11 = s_w10 + K * TILE_P;

    const int wo0 = blockIdx.x * TILE_P;
    const int ho  = blockIdx.y;
    const int b   = blockIdx.z;

    const int tid    = threadIdx.x;
    const int warpId = tid >> 5;
    const int lane   = tid & 31;

    // ---- Phase 0: per-(k, pixel) sampling positions + bilinear weights*mask
    // NOTE: K*TILE_P = 288 > NTHREADS, so stride the loop (R2 bugfix).
    for (int t = tid; t < K * TILE_P; t += NTHREADS) {
        int k = t >> 5;            // 0..8
        int p = t & 31;
        int wo = wo0 + p;
        float offy = offset[((b * 2 * K + 2 * k    ) * H + ho) * W + wo];
        float offx = offset[((b * 2 * K + 2 * k + 1) * H + ho) * W + wo];
        float m    = mask  [((b * K + k) * H + ho) * W + wo];
        float py = offy + (float)(k / KW) + (float)(ho - 1);   // dh=1, ph=1, sh=1
        float px = offx + (float)(k % KW) + (float)(wo - 1);
        float y0f = floorf(py), x0f = floorf(px);
        float ly = py - y0f, lx = px - x0f;
        s_y0[t] = (int)y0f;
        s_x0[t] = (int)x0f;
        s_w00[t] = (1.f - ly) * (1.f - lx) * m;
        s_w01[t] = (1.f - ly) * lx * m;
        s_w10[t] = ly * (1.f - lx) * m;
        s_w11[t] = ly * lx * m;
    }
    __syncthreads();

    // ---- Phase 1: sampling. Warp-per-task, lane = channel pair (NHWC coalesced)
    const float* xb = g_xt + (size_t)b * HW * C;
    #pragma unroll 1
    for (int i = 0; i < (K * TILE_P) / 8; i++) {   // 36 tasks per warp
        int t = warpId * 36 + i;
        int k = t >> 5;
        int p = t & 31;
        int y0 = s_y0[t];
        int x0 = s_x0[t];
        float w00 = s_w00[t], w01 = s_w01[t], w10 = s_w10[t], w11 = s_w11[t];

        float2 v00 = {0.f, 0.f}, v01 = {0.f, 0.f}, v10 = {0.f, 0.f}, v11 = {0.f, 0.f};
        bool yv0 = (unsigned)y0 < H;
        bool yv1 = (unsigned)(y0 + 1) < H;
        bool xv0 = (unsigned)x0 < W;
        bool xv1 = (unsigned)(x0 + 1) < W;
        int coff = lane * 2;
        if (yv0 && xv0) v00 = *(const float2*)(xb + ((y0    ) * W + x0    ) * C + coff);
        if (yv0 && xv1) v01 = *(const float2*)(xb + ((y0    ) * W + x0 + 1) * C + coff);
        if (yv1 && xv0) v10 = *(const float2*)(xb + ((y0 + 1) * W + x0    ) * C + coff);
        if (yv1 && xv1) v11 = *(const float2*)(xb + ((y0 + 1) * W + x0 + 1) * C + coff);

        float r0 = w00 * v00.x + w01 * v01.x + w10 * v10.x + w11 * v11.x;
        float r1 = w00 * v00.y + w01 * v01.y + w10 * v10.y + w11 * v11.y;
        int ckbase = p * CK + coff * K + k;   // val[p][c*9+k]
        val[ckbase]     = r0;
        val[ckbase + K] = r1;
    }
    __syncthreads();

    // ---- Phase 2: out[o][p] = sum_ck Wq * val   (lanes = o, 8 pixels/thread)
    const int h = warpId & 1;          // o half
    const int g = warpId >> 1;         // pixel group (8 pixels)
    const int o = h * 32 + lane;

    float acc0 = 0.f, acc1 = 0.f, acc2 = 0.f, acc3 = 0.f;
    float acc4 = 0.f, acc5 = 0.f, acc6 = 0.f, acc7 = 0.f;

    const float4* wq = (const float4*)g_wq;        // [CK/4][O]
    const float* vbase = val + (g * 8) * CK;

    #pragma unroll 2
    for (int cb = 0; cb < CK / 4; cb++) {
        float4 wv = wq[cb * O + o];
        const float* vp = vbase + cb * 4;
        float4 v;
        v = *(const float4*)(vp + 0 * CK); acc0 += wv.x*v.x + wv.y*v.y + wv.z*v.z + wv.w*v.w;
        v = *(const float4*)(vp + 1 * CK); acc1 += wv.x*v.x + wv.y*v.y + wv.z*v.z + wv.w*v.w;
        v = *(const float4*)(vp + 2 * CK); acc2 += wv.x*v.x + wv.y*v.y + wv.z*v.z + wv.w*v.w;
        v = *(const float4*)(vp + 3 * CK); acc3 += wv.x*v.x + wv.y*v.y + wv.z*v.z + wv.w*v.w;
        v = *(const float4*)(vp + 4 * CK); acc4 += wv.x*v.x + wv.y*v.y + wv.z*v.z + wv.w*v.w;
        v = *(const float4*)(vp + 5 * CK); acc5 += wv.x*v.x + wv.y*v.y + wv.z*v.z + wv.w*v.w;
        v = *(const float4*)(vp + 6 * CK); acc6 += wv.x*v.x + wv.y*v.y + wv.z*v.z + wv.w*v.w;
        v = *(const float4*)(vp + 7 * CK); acc7 += wv.x*v.x + wv.y*v.y + wv.z*v.z + wv.w*v.w;
    }

    float bv = bias[o];
    float* ob = out + (((size_t)b * O + o) * H + ho) * W + wo0 + g * 8;
    float4 r0 = {acc0 + bv, acc1 + bv, acc2 + bv, acc3 + bv};
    float4 r1 = {acc4 + bv, acc5 + bv, acc6 + bv, acc7 + bv};
    *(float4*)(ob)     = r0;
    *(float4*)(ob + 4) = r1;
}

// ---------------------------------------------------------------------------
extern "C" void kernel_launch(void* const* d_in, const int* in_sizes, int n_in,
                              void* d_out, int out_size) {
    const float* x      = (const float*)d_in[0];
    const float* offset = (const float*)d_in[1];
    const float* mask   = (const float*)d_in[2];
    const float* weight = (const float*)d_in[3];
    const float* bias   = (const float*)d_in[4];
    float* out = (float*)d_out;

    // A: transpose to NHWC
    {
        dim3 grid(HW / 32, C / 32, B);
        dim3 block(32, 8);
        transpose_kernel<<<grid, block>>>(x);
    }
    // B: weight repack
    {
        wq_kernel<<<(CK * O + 255) / 256, 256>>>(weight);
    }
    // C: main
    {
        int smem_bytes = (TILE_P * CK + 6 * K * TILE_P) * sizeof(float);  // ~80.6KB
        cudaFuncSetAttribute(deform_main_kernel,
                             cudaFuncAttributeMaxDynamicSharedMemorySize, smem_bytes);
        dim3 grid(W / TILE_P, H, B);
        deform_main_kernel<<<grid, NTHREADS, smem_bytes>>>(offset, mask, bias, out);
    }
}